// round 1
// baseline (speedup 1.0000x reference)
#include <cuda_runtime.h>

// CGCoupler: out[n, ro[m]] += x1[n, r1[m]] * x2[n, r2[m]] * cg[m]
// Strategy:
//   prep_kernel (1 CTA): counting-sort the M sparse entries by output slot into
//     a CSR structure in __device__ globals: seg_ptr[out_dim+1] and packed
//     entries {r1 | r2<<16, cg} (8 B each).
//   couple_kernel: one CTA per 16 batch rows. Entry table + seg ptrs loaded to
//     smem once per CTA. Rows processed in pairs: x1/x2 rows staged interleaved
//     as float2 in smem so one LDS.64 serves both rows. Each thread owns output
//     slots -> segment-sum, no atomics, coalesced global stores.

#define N_BATCH 16384
#define ROWS    16
#define TPB     256
#define MAX_M   32768
#define MAX_OUT 4096

__device__ uint2 g_entries[MAX_M];
__device__ int   g_segptr[MAX_OUT + 1];

__global__ void prep_kernel(const void* r1v, const void* r2v, const void* rov,
                            const float* __restrict__ cg, int M, int out_dim) {
    __shared__ int hist[MAX_OUT + 1];
    __shared__ int warp_sums[32];
    __shared__ int s_is64;
    int tid = threadIdx.x, bd = blockDim.x;

    // dtype auto-detect: int64 little-endian small values => all odd 32-bit words zero
    if (tid == 0) {
        const unsigned* w = (const unsigned*)r1v;
        int nw = 2 * M; if (nw > 256) nw = 256;
        int is64 = 1;
        for (int i = 1; i < nw; i += 2) if (w[i] != 0u) { is64 = 0; break; }
        s_is64 = is64;
    }
    int n = out_dim + 1;
    for (int i = tid; i < n; i += bd) hist[i] = 0;
    __syncthreads();
    int is64 = s_is64;
    const int*       ro32 = (const int*)rov;
    const long long* ro64 = (const long long*)rov;
    const int*       r132 = (const int*)r1v;
    const long long* r164 = (const long long*)r1v;
    const int*       r232 = (const int*)r2v;
    const long long* r264 = (const long long*)r2v;

    for (int m = tid; m < M; m += bd) {
        int o = is64 ? (int)ro64[m] : ro32[m];
        atomicAdd(&hist[o + 1], 1);
    }
    __syncthreads();

    // inclusive block scan over hist[0..n-1]  (hist[o+1] held count(slot o))
    int CH = (n + bd - 1) / bd;
    int base = tid * CH;
    int local = 0;
    for (int i = 0; i < CH; i++) { int idx = base + i; if (idx < n) local += hist[idx]; }
    int lane = tid & 31, wid = tid >> 5;
    int v = local;
    #pragma unroll
    for (int d = 1; d < 32; d <<= 1) { int t = __shfl_up_sync(0xffffffffu, v, d); if (lane >= d) v += t; }
    if (lane == 31) warp_sums[wid] = v;
    __syncthreads();
    if (wid == 0) {
        int nw = bd >> 5;
        int w = (lane < nw) ? warp_sums[lane] : 0;
        #pragma unroll
        for (int d = 1; d < 32; d <<= 1) { int t = __shfl_up_sync(0xffffffffu, w, d); if (lane >= d) w += t; }
        warp_sums[lane] = w;
    }
    __syncthreads();
    int prefix = (v - local) + (wid > 0 ? warp_sums[wid - 1] : 0);
    int run = prefix;
    for (int i = 0; i < CH; i++) {
        int idx = base + i;
        if (idx < n) { run += hist[idx]; hist[idx] = run; }
    }
    __syncthreads();
    // hist[o] now = start of slot o's segment; hist[out_dim] = M
    for (int i = tid; i < n; i += bd) g_segptr[i] = hist[i];
    __syncthreads();
    // scatter entries into CSR order (order within a segment is arbitrary; fp-add commutes within tol)
    for (int m = tid; m < M; m += bd) {
        int o = is64 ? (int)ro64[m] : ro32[m];
        int a = is64 ? (int)r164[m] : r132[m];
        int b = is64 ? (int)r264[m] : r232[m];
        int pos = atomicAdd(&hist[o], 1);
        g_entries[pos] = make_uint2((unsigned)a | ((unsigned)b << 16), __float_as_uint(cg[m]));
    }
}

__global__ void __launch_bounds__(TPB)
couple_kernel(const float* __restrict__ x1, const float* __restrict__ x2,
              float* __restrict__ out, int rep_dim, int out_dim,
              int M, int entries_in_smem) {
    extern __shared__ char smraw[];
    float2* x1s = (float2*)smraw;                       // rep_dim float2 (row pair interleaved)
    float2* x2s = x1s + rep_dim;                        // rep_dim float2
    int*    sp  = (int*)(x2s + rep_dim);                // out_dim+1 (padded to even)
    int spn = (out_dim + 2) & ~1;
    uint2*  es_s = (uint2*)(sp + spn);                  // M entries (if they fit)
    const uint2* es = entries_in_smem ? (const uint2*)es_s : (const uint2*)g_entries;

    int tid = threadIdx.x;
    if (entries_in_smem)
        for (int i = tid; i < M; i += TPB) es_s[i] = g_entries[i];
    for (int i = tid; i <= out_dim; i += TPB) sp[i] = g_segptr[i];

    int row0 = blockIdx.x * ROWS;
    for (int rp = 0; rp < ROWS; rp += 2) {
        int ra = row0 + rp, rb = ra + 1;
        __syncthreads();   // previous pair consumed (and 1st iter: smem tables loaded)
        const float* pa1 = x1 + (size_t)ra * rep_dim;
        const float* pb1 = x1 + (size_t)rb * rep_dim;
        const float* pa2 = x2 + (size_t)ra * rep_dim;
        const float* pb2 = x2 + (size_t)rb * rep_dim;
        for (int i = tid; i < rep_dim; i += TPB) {
            x1s[i] = make_float2(pa1[i], pb1[i]);
            x2s[i] = make_float2(pa2[i], pb2[i]);
        }
        __syncthreads();
        float* oa = out + (size_t)ra * out_dim;
        float* ob = out + (size_t)rb * out_dim;
        for (int o = tid; o < out_dim; o += TPB) {
            int s = sp[o], e = sp[o + 1];
            float acc0 = 0.f, acc1 = 0.f;
            for (int j = s; j < e; j++) {
                uint2 en = es[j];
                float c = __uint_as_float(en.y);
                float2 va = x1s[en.x & 0xffffu];
                float2 vb = x2s[en.x >> 16];
                acc0 = fmaf(va.x * vb.x, c, acc0);
                acc1 = fmaf(va.y * vb.y, c, acc1);
            }
            oa[o] = acc0;
            ob[o] = acc1;
        }
    }
}

extern "C" void kernel_launch(void* const* d_in, const int* in_sizes, int n_in,
                              void* d_out, int out_size) {
    const float* x1 = (const float*)d_in[0];
    const float* x2 = (const float*)d_in[1];
    const float* cg = (const float*)d_in[2];
    const void*  r1 = d_in[3];
    const void*  r2 = d_in[4];
    const void*  ro = d_in[5];
    int M = in_sizes[2];
    int rep_dim = in_sizes[0] / N_BATCH;
    int out_dim = out_size / N_BATCH;

    prep_kernel<<<1, 1024>>>(r1, r2, ro, cg, M, out_dim);

    int spn = (out_dim + 2) & ~1;
    size_t smem = (size_t)rep_dim * 16 + (size_t)spn * 4 + (size_t)M * 8;
    int fit = (smem <= 200 * 1024);
    if (!fit) smem = (size_t)rep_dim * 16 + (size_t)spn * 4;

    cudaFuncSetAttribute(couple_kernel,
                         cudaFuncAttributeMaxDynamicSharedMemorySize, 210 * 1024);
    couple_kernel<<<N_BATCH / ROWS, TPB, smem>>>(
        x1, x2, (float*)d_out, rep_dim, out_dim, M, fit);
}

// round 3
// speedup vs baseline: 1.5890x; 1.5890x over previous
#include <cuda_runtime.h>

// CGCoupler: out[n, ro[m]] += x1[n, r1[m]] * x2[n, r2[m]] * cg[m]
//
// Structure exploit: the index arrays are path-major runs: each CG path is
// expanded over a dense channel dim ns=0..deg-1 with r1/r2/ro consecutive and
// cg identical. Prep compresses entries -> paths {r1_0,r2_0,cg,deg}, bins by
// output-group base ro_0, and builds a per-column {path_start,count,ns} map.
// Compute: thread owns output column; path records broadcast from smem (free),
// x-value gathers are lane-consecutive -> conflict-free LDS.128 over 4 rows.

#define N_BATCH 16384
#define ROWS    16
#define RPT     4
#define TPB     256
#define MAX_P   4096
#define MAX_OUT 2048
#define P_SMEM  512

__device__ uint4 g_paths[MAX_P];      // {r1_0, r2_0, cg_bits, deg}, binned by group
__device__ int4  g_colinfo[MAX_OUT];  // {path_start, path_count, ns, 0}
__device__ int   g_pstart[MAX_P + 1];
__device__ int   g_pro[MAX_P];
__device__ uint4 g_paths_raw[MAX_P];
__device__ int   g_npaths;

__device__ __forceinline__ int block_incl_scan(int v, int tid) {
    __shared__ int ws[32];
    int lane = tid & 31, wid = tid >> 5;
    __syncthreads();                       // protect ws across successive calls
    #pragma unroll
    for (int d = 1; d < 32; d <<= 1) {
        int t = __shfl_up_sync(0xffffffffu, v, d);
        if (lane >= d) v += t;
    }
    if (lane == 31) ws[wid] = v;
    __syncthreads();
    if (wid == 0) {
        int w = ws[lane];
        #pragma unroll
        for (int d = 1; d < 32; d <<= 1) {
            int t = __shfl_up_sync(0xffffffffu, w, d);
            if (lane >= d) w += t;
        }
        ws[lane] = w;
    }
    __syncthreads();
    return v + (wid > 0 ? ws[wid - 1] : 0);
}

__global__ void prep_kernel(const void* r1v, const void* r2v, const void* rov,
                            const float* __restrict__ cg, int M, int out_dim) {
    __shared__ int s_is64, s_carry;
    __shared__ int cnt[MAX_OUT + 1];
    __shared__ int st[MAX_OUT + 1];
    int tid = threadIdx.x, bd = blockDim.x;

    // dtype auto-detect: int64 little-endian small values -> odd 32-bit words zero
    if (tid == 0) {
        const unsigned* w = (const unsigned*)r1v;
        int nw = 2 * M; if (nw > 256) nw = 256;
        int is64 = 1;
        for (int i = 1; i < nw; i += 2) if (w[i] != 0u) { is64 = 0; break; }
        s_is64 = is64;
        s_carry = 0;
    }
    __syncthreads();
    int is64 = s_is64;
    const int*       r132 = (const int*)r1v;       const long long* r164 = (const long long*)r1v;
    const int*       r232 = (const int*)r2v;       const long long* r264 = (const long long*)r2v;
    const int*       ro32 = (const int*)rov;       const long long* ro64 = (const long long*)rov;
    const unsigned*  cgu  = (const unsigned*)cg;
    #define IDX1(m) (is64 ? (int)r164[m] : r132[m])
    #define IDX2(m) (is64 ? (int)r264[m] : r232[m])
    #define IDXO(m) (is64 ? (int)ro64[m] : ro32[m])

    // ---- Phase A: find run (path) starts, chunked block scan ----
    for (int base = 0; base < M; base += bd) {
        int m = base + tid;
        int f = 0;
        if (m < M) {
            if (m == 0) f = 1;
            else {
                int a = IDX1(m), ap = IDX1(m - 1);
                int b = IDX2(m), bp = IDX2(m - 1);
                int c = IDXO(m), cp = IDXO(m - 1);
                f = !(a == ap + 1 && b == bp + 1 && c == cp + 1 && cgu[m] == cgu[m - 1]);
            }
        }
        int incl = block_incl_scan(f, tid);
        int carry = s_carry;
        int pid = carry + incl;
        if (m < M && f) g_pstart[pid - 1] = m;
        __syncthreads();
        if (tid == bd - 1) s_carry = pid;
        __syncthreads();
    }
    int P = s_carry;
    if (tid == 0) { g_npaths = P; g_pstart[P] = M; }
    __syncthreads();

    // ---- Phase B: materialize raw paths ----
    for (int p = tid; p < P; p += bd) {
        int s = g_pstart[p];
        int deg = g_pstart[p + 1] - s;
        g_paths_raw[p] = make_uint4((unsigned)IDX1(s), (unsigned)IDX2(s),
                                    cgu[s], (unsigned)deg);
        g_pro[p] = IDXO(s);
    }
    int n = out_dim + 1;
    for (int i = tid; i < n; i += bd) cnt[i] = 0;
    __syncthreads();

    // ---- Phase C: bin paths by group base ro_0 ----
    for (int p = tid; p < P; p += bd) atomicAdd(&cnt[g_pro[p]], 1);
    __syncthreads();

    // exclusive prefix of cnt -> st (chunked)
    int CH = (n + bd - 1) / bd;
    int cb = tid * CH;
    int local = 0;
    for (int i = 0; i < CH; i++) { int idx = cb + i; if (idx < n) local += cnt[idx]; }
    int incl = block_incl_scan(local, tid);
    int run = incl - local;
    for (int i = 0; i < CH; i++) {
        int idx = cb + i;
        if (idx < n) { st[idx] = run; run += cnt[idx]; }
    }
    __syncthreads();

    // per-column info (before scatter destroys st cursors? use separate pass:
    // colinfo only reads st/cnt, scatter mutates a copy via atomics on st AFTER)
    for (int c = tid; c < out_dim; c += bd) {
        int b = c;
        while (b >= 0 && cnt[b] == 0) b--;
        if (b < 0) g_colinfo[c] = make_int4(0, 0, 0, 0);
        else       g_colinfo[c] = make_int4(st[b], cnt[b], c - b, 0);
    }
    __syncthreads();
    for (int p = tid; p < P; p += bd) {
        int pos = atomicAdd(&st[g_pro[p]], 1);
        g_paths[pos] = g_paths_raw[p];
    }
    #undef IDX1
    #undef IDX2
    #undef IDXO
}

__global__ void __launch_bounds__(TPB)
couple_kernel(const float* __restrict__ x1, const float* __restrict__ x2,
              float* __restrict__ out, int rep_dim, int out_dim) {
    extern __shared__ char smraw[];
    float4* x1s = (float4*)smraw;              // rep_dim float4 (4 rows interleaved)
    float4* x2s = x1s + rep_dim;               // rep_dim float4
    int4*   ci  = (int4*)(x2s + rep_dim);      // out_dim
    uint4*  pts = (uint4*)(ci + out_dim);      // P_SMEM paths

    int tid = threadIdx.x;
    int P = g_npaths;
    int pl = P < P_SMEM ? P : P_SMEM;
    for (int i = tid; i < pl; i += TPB) pts[i] = g_paths[i];
    for (int i = tid; i < out_dim; i += TPB) ci[i] = g_colinfo[i];
    const uint4* pp = (P <= P_SMEM) ? (const uint4*)pts : (const uint4*)g_paths;

    int row0 = blockIdx.x * ROWS;
    for (int t = 0; t < ROWS; t += RPT) {
        int r = row0 + t;
        __syncthreads();   // prior tile consumed / tables loaded
        const float* a0 = x1 + (size_t)r * rep_dim;
        const float* a1 = a0 + rep_dim;
        const float* a2 = a1 + rep_dim;
        const float* a3 = a2 + rep_dim;
        const float* b0 = x2 + (size_t)r * rep_dim;
        const float* b1 = b0 + rep_dim;
        const float* b2 = b1 + rep_dim;
        const float* b3 = b2 + rep_dim;
        for (int i = tid; i < rep_dim; i += TPB) {
            x1s[i] = make_float4(a0[i], a1[i], a2[i], a3[i]);
            x2s[i] = make_float4(b0[i], b1[i], b2[i], b3[i]);
        }
        __syncthreads();
        for (int o = tid; o < out_dim; o += TPB) {
            int4 c = ci[o];
            int s = c.x, np = c.y;
            unsigned ns = (unsigned)c.z;
            float4 acc = make_float4(0.f, 0.f, 0.f, 0.f);
            for (int j = 0; j < np; j++) {
                uint4 p = pp[s + j];                 // uniform across warp: broadcast
                if (ns < p.w) {
                    float cgv = __uint_as_float(p.z);
                    float4 A = x1s[p.x + ns];        // lane-consecutive: conflict-free
                    float4 B = x2s[p.y + ns];
                    acc.x = fmaf(A.x * B.x, cgv, acc.x);
                    acc.y = fmaf(A.y * B.y, cgv, acc.y);
                    acc.z = fmaf(A.z * B.z, cgv, acc.z);
                    acc.w = fmaf(A.w * B.w, cgv, acc.w);
                }
            }
            out[(size_t)r * out_dim + o]       = acc.x;
            out[(size_t)(r + 1) * out_dim + o] = acc.y;
            out[(size_t)(r + 2) * out_dim + o] = acc.z;
            out[(size_t)(r + 3) * out_dim + o] = acc.w;
        }
    }
}

extern "C" void kernel_launch(void* const* d_in, const int* in_sizes, int n_in,
                              void* d_out, int out_size) {
    const float* x1 = (const float*)d_in[0];
    const float* x2 = (const float*)d_in[1];
    const float* cg = (const float*)d_in[2];
    const void*  r1 = d_in[3];
    const void*  r2 = d_in[4];
    const void*  ro = d_in[5];
    int M = in_sizes[2];
    int rep_dim = in_sizes[0] / N_BATCH;
    int out_dim = out_size / N_BATCH;

    prep_kernel<<<1, 1024>>>(r1, r2, ro, cg, M, out_dim);

    size_t smem = (size_t)rep_dim * 32 + (size_t)out_dim * 16 + (size_t)P_SMEM * 16;
    cudaFuncSetAttribute(couple_kernel,
                         cudaFuncAttributeMaxDynamicSharedMemorySize, 160 * 1024);
    couple_kernel<<<N_BATCH / ROWS, TPB, smem>>>(x1, x2, (float*)d_out,
                                                 rep_dim, out_dim);
}

// round 5
// speedup vs baseline: 1.6995x; 1.0696x over previous
#include <cuda_runtime.h>

// CGCoupler: out[n, ro[m]] += x1[n, r1[m]] * x2[n, r2[m]] * cg[m]
//
// Paths: index arrays are path-major runs (r1/r2/ro consecutive, cg equal) over
// a dense channel dim ns=0..deg-1. Prep compresses entries -> paths
// {r1_0,r2_0,cg,deg}, bins by output base ro_0, sorts each bin by deg DESC, and
// builds per-column {path_start, ns, eff_count} (eff = #paths with deg > ns) so
// the compute inner loop has no predicate and no wasted iterations.
// Compute: thread owns output columns; path records broadcast from smem, x-value
// gathers lane-consecutive -> conflict-free LDS.128 over 4 interleaved rows.
// Staging is software-pipelined through registers (LDG overlap with compute).

#define N_BATCH 16384
#define ROWS    16
#define RPT     4
#define NT      (ROWS / RPT)
#define TPB     320
#define MAX_P   4096
#define MAX_OUT 2048
#define P_SMEM  256
#define KMAX    4      // supports rep_dim <= KMAX*TPB

__device__ uint4 g_paths[MAX_P];      // {r1_0, r2_0, cg_bits, deg} binned, deg-desc in bin
__device__ uint2 g_colinfo[MAX_OUT];  // {start | ns<<16, eff}
__device__ int   g_pstart[MAX_P + 1];
__device__ int   g_pro[MAX_P];
__device__ uint4 g_paths_raw[MAX_P];
__device__ int   g_npaths;

__device__ __forceinline__ int block_incl_scan(int v, int tid) {
    __shared__ int ws[32];
    int lane = tid & 31, wid = tid >> 5;
    __syncthreads();                       // protect ws across successive calls
    #pragma unroll
    for (int d = 1; d < 32; d <<= 1) {
        int t = __shfl_up_sync(0xffffffffu, v, d);
        if (lane >= d) v += t;
    }
    if (lane == 31) ws[wid] = v;
    __syncthreads();
    if (wid == 0) {
        int w = ws[lane];
        #pragma unroll
        for (int d = 1; d < 32; d <<= 1) {
            int t = __shfl_up_sync(0xffffffffu, w, d);
            if (lane >= d) w += t;
        }
        ws[lane] = w;
    }
    __syncthreads();
    return v + (wid > 0 ? ws[wid - 1] : 0);
}

__global__ void prep_kernel(const void* r1v, const void* r2v, const void* rov,
                            const float* __restrict__ cg, int M, int out_dim) {
    __shared__ int s_is64, s_carry;
    __shared__ int cnt[MAX_OUT + 1];
    __shared__ int st[MAX_OUT + 1];
    int tid = threadIdx.x, bd = blockDim.x;

    // dtype auto-detect (parallel): int64 little-endian small values
    // -> odd 32-bit words all zero. Only scan the first M words (safe for int32).
    if (tid == 0) { s_is64 = 1; s_carry = 0; }
    __syncthreads();
    {
        const unsigned* w = (const unsigned*)r1v;
        int nw = M < 4096 ? M : 4096;
        for (int i = 1 + 2 * tid; i < nw; i += 2 * bd)
            if (w[i] != 0u) s_is64 = 0;   // benign race
    }
    __syncthreads();
    int is64 = s_is64;
    const int*       r132 = (const int*)r1v;       const long long* r164 = (const long long*)r1v;
    const int*       r232 = (const int*)r2v;       const long long* r264 = (const long long*)r2v;
    const int*       ro32 = (const int*)rov;       const long long* ro64 = (const long long*)rov;
    const unsigned*  cgu  = (const unsigned*)cg;
    #define IDX1(m) (is64 ? (int)r164[m] : r132[m])
    #define IDX2(m) (is64 ? (int)r264[m] : r232[m])
    #define IDXO(m) (is64 ? (int)ro64[m] : ro32[m])

    // ---- Phase A: find run (path) starts, chunked block scan ----
    for (int base = 0; base < M; base += bd) {
        int m = base + tid;
        int f = 0;
        if (m < M) {
            if (m == 0) f = 1;
            else {
                int a = IDX1(m), ap = IDX1(m - 1);
                int b = IDX2(m), bp = IDX2(m - 1);
                int c = IDXO(m), cp = IDXO(m - 1);
                f = !(a == ap + 1 && b == bp + 1 && c == cp + 1 && cgu[m] == cgu[m - 1]);
            }
        }
        int incl = block_incl_scan(f, tid);
        int carry = s_carry;
        int pid = carry + incl;
        if (m < M && f) g_pstart[pid - 1] = m;
        __syncthreads();
        if (tid == bd - 1) s_carry = pid;
        __syncthreads();
    }
    int P = s_carry;
    if (tid == 0) { g_npaths = P; g_pstart[P] = M; }
    __syncthreads();

    // ---- Phase B: materialize raw paths ----
    for (int p = tid; p < P; p += bd) {
        int s = g_pstart[p];
        int deg = g_pstart[p + 1] - s;
        g_paths_raw[p] = make_uint4((unsigned)IDX1(s), (unsigned)IDX2(s),
                                    cgu[s], (unsigned)deg);
        g_pro[p] = IDXO(s);
    }
    int n = out_dim + 1;
    for (int i = tid; i < n; i += bd) cnt[i] = 0;
    __syncthreads();

    // ---- Phase C: bin paths by group base ro_0 ----
    for (int p = tid; p < P; p += bd) atomicAdd(&cnt[g_pro[p]], 1);
    __syncthreads();

    // exclusive prefix of cnt -> st (chunked)
    int CH = (n + bd - 1) / bd;
    int cb = tid * CH;
    int local = 0;
    for (int i = 0; i < CH; i++) { int idx = cb + i; if (idx < n) local += cnt[idx]; }
    int incl = block_incl_scan(local, tid);
    int run = incl - local;
    for (int i = 0; i < CH; i++) {
        int idx = cb + i;
        if (idx < n) { st[idx] = run; run += cnt[idx]; }
    }
    __syncthreads();

    // scatter into bins (st becomes end-cursor per bin)
    for (int p = tid; p < P; p += bd) {
        int pos = atomicAdd(&st[g_pro[p]], 1);
        g_paths[pos] = g_paths_raw[p];
    }
    __syncthreads();

    // ---- Phase D: sort each bin by deg DESC (tiny bins, insertion sort) ----
    for (int b = tid; b < out_dim; b += bd) {
        int c0 = cnt[b];
        if (c0 > 1) {
            int s0 = st[b] - c0;
            for (int i = 1; i < c0; i++) {
                uint4 key = g_paths[s0 + i];
                int j = i - 1;
                while (j >= 0 && g_paths[s0 + j].w < key.w) {
                    g_paths[s0 + j + 1] = g_paths[s0 + j]; j--;
                }
                g_paths[s0 + j + 1] = key;
            }
        }
    }
    __syncthreads();

    // ---- Phase E: per-column info with effective counts ----
    for (int c = tid; c < out_dim; c += bd) {
        int b = c;
        while (b >= 0 && cnt[b] == 0) b--;
        uint2 info = make_uint2(0u, 0u);
        if (b >= 0) {
            int c0 = cnt[b];
            int s0 = st[b] - c0;
            int ns = c - b;
            int eff = 0;
            while (eff < c0 && (int)g_paths[s0 + eff].w > ns) eff++;
            info = make_uint2((unsigned)s0 | ((unsigned)ns << 16), (unsigned)eff);
        }
        g_colinfo[c] = info;
    }
    #undef IDX1
    #undef IDX2
    #undef IDXO
}

__global__ void __launch_bounds__(TPB)
couple_kernel(const float* __restrict__ x1, const float* __restrict__ x2,
              float* __restrict__ out, int rep_dim, int out_dim) {
    extern __shared__ char smraw[];
    float4* x1s = (float4*)smraw;              // rep_dim float4 (4 rows interleaved)
    float4* x2s = x1s + rep_dim;
    uint2*  ci  = (uint2*)(x2s + rep_dim);     // out_dim
    uint4*  pts = (uint4*)(ci + ((out_dim + 1) & ~1));  // P_SMEM paths

    int tid = threadIdx.x;
    int P = g_npaths;
    int pl = P < P_SMEM ? P : P_SMEM;
    for (int i = tid; i < pl; i += TPB) pts[i] = g_paths[i];
    for (int i = tid; i < out_dim; i += TPB) ci[i] = g_colinfo[i];
    const uint4* pp = (P <= P_SMEM) ? (const uint4*)pts : (const uint4*)g_paths;

    int row0 = blockIdx.x * ROWS;

    // stage tile 0 directly
    {
        const float* a0 = x1 + (size_t)row0 * rep_dim;
        const float* b0 = x2 + (size_t)row0 * rep_dim;
        for (int i = tid; i < rep_dim; i += TPB) {
            x1s[i] = make_float4(a0[i], a0[i + rep_dim], a0[i + 2 * rep_dim], a0[i + 3 * rep_dim]);
            x2s[i] = make_float4(b0[i], b0[i + rep_dim], b0[i + 2 * rep_dim], b0[i + 3 * rep_dim]);
        }
    }
    __syncthreads();

    for (int t = 0; t < NT; t++) {
        int r = row0 + t * RPT;

        // prefetch next tile into registers (LDG in flight during compute)
        float4 pa[KMAX], pb[KMAX];
        if (t + 1 < NT) {
            const float* a0 = x1 + (size_t)(r + RPT) * rep_dim;
            const float* b0 = x2 + (size_t)(r + RPT) * rep_dim;
            #pragma unroll
            for (int k = 0; k < KMAX; k++) {
                int i = tid + k * TPB;
                if (i < rep_dim) {
                    pa[k] = make_float4(a0[i], a0[i + rep_dim], a0[i + 2 * rep_dim], a0[i + 3 * rep_dim]);
                    pb[k] = make_float4(b0[i], b0[i + rep_dim], b0[i + 2 * rep_dim], b0[i + 3 * rep_dim]);
                }
            }
        }

        // compute current tile
        for (int o = tid; o < out_dim; o += TPB) {
            uint2 c = ci[o];
            int s = (int)(c.x & 0xffffu);
            unsigned ns = c.x >> 16;
            int ne = (int)c.y;
            float4 acc = make_float4(0.f, 0.f, 0.f, 0.f);
            #pragma unroll 2
            for (int j = 0; j < ne; j++) {
                uint4 p = pp[s + j];                 // warp-uniform: broadcast
                float cgv = __uint_as_float(p.z);
                float4 A = x1s[p.x + ns];            // lane-consecutive: conflict-free
                float4 B = x2s[p.y + ns];
                acc.x = fmaf(A.x * B.x, cgv, acc.x);
                acc.y = fmaf(A.y * B.y, cgv, acc.y);
                acc.z = fmaf(A.z * B.z, cgv, acc.z);
                acc.w = fmaf(A.w * B.w, cgv, acc.w);
            }
            float* ob = out + (size_t)r * out_dim + o;
            ob[0]                   = acc.x;
            ob[(size_t)out_dim]     = acc.y;
            ob[(size_t)out_dim * 2] = acc.z;
            ob[(size_t)out_dim * 3] = acc.w;
        }
        __syncthreads();   // everyone done reading the buffer

        if (t + 1 < NT) {
            #pragma unroll
            for (int k = 0; k < KMAX; k++) {
                int i = tid + k * TPB;
                if (i < rep_dim) { x1s[i] = pa[k]; x2s[i] = pb[k]; }
            }
            __syncthreads();   // buffer ready for next tile
        }
    }
}

extern "C" void kernel_launch(void* const* d_in, const int* in_sizes, int n_in,
                              void* d_out, int out_size) {
    const float* x1 = (const float*)d_in[0];
    const float* x2 = (const float*)d_in[1];
    const float* cg = (const float*)d_in[2];
    const void*  r1 = d_in[3];
    const void*  r2 = d_in[4];
    const void*  ro = d_in[5];
    int M = in_sizes[2];
    int rep_dim = in_sizes[0] / N_BATCH;
    int out_dim = out_size / N_BATCH;

    prep_kernel<<<1, 1024>>>(r1, r2, ro, cg, M, out_dim);

    size_t smem = (size_t)rep_dim * 32 + (size_t)((out_dim + 1) & ~1) * 8
                + (size_t)P_SMEM * 16;
    cudaFuncSetAttribute(couple_kernel,
                         cudaFuncAttributeMaxDynamicSharedMemorySize, 160 * 1024);
    couple_kernel<<<N_BATCH / ROWS, TPB, smem>>>(x1, x2, (float*)d_out,
                                                 rep_dim, out_dim);
}